// round 4
// baseline (speedup 1.0000x reference)
#include <cuda_runtime.h>

#define EPS 1e-5f

#define B   32
#define C   256
#define CCH 64      // CC
#define HS  64
#define PS  4096    // 64*64
#define PT  196     // 14*14

// ---------------- scratch (device globals: no allocation allowed) ----------------
__device__ float g_t   [B * CCH * PT];            // normalized template features
__device__ float g_tk  [B * CCH * 49];            // 7x7 depthwise kernels
__device__ float g_tg  [B * CCH];                 // template global means
__device__ float g_z   [(size_t)B * CCH * PS];    // raw search conv1x1 output
__device__ float g_corr[(size_t)B * CCH * PS];    // global + local correlation
__device__ float g_y   [(size_t)B * CCH * PS];    // raw conv3x3 output
__device__ float g_ab_s[B * CCH * 2];             // GN affine (alpha,beta) search
__device__ float g_ab_p[B * CCH * 2];             // GN affine (alpha,beta) post
__device__ float g_wT  [CCH * 9 * CCH];           // w_p1 transposed: [cin][k][co]

// =============================================================================
// K1: template branch: conv1x1 (256->64) + GroupNorm(32 groups) + ReLU
// one block per batch sample; 8cc x 7px register tile per thread
// =============================================================================
__global__ __launch_bounds__(256) void k_template(
    const float* __restrict__ tf, const float* __restrict__ w_t,
    const float* __restrict__ gnw, const float* __restrict__ gnb)
{
    __shared__ __align__(16) float smem[32 * 224 + 32 * 68]; // xs[32][224] + ws[32][68]
    float* xs = smem;
    float* ws = smem + 32 * 224;
    __shared__ float gm[32], grs[32];

    int b = blockIdx.x, t = threadIdx.x;
    int ccg = t >> 5;       // 0..7  (owns cc = ccg*8 .. +7)
    int pt  = t & 31;       // 0..31 (owns p = pt + 32*j)

    float acc[8][7];
#pragma unroll
    for (int i = 0; i < 8; i++)
#pragma unroll
        for (int j = 0; j < 7; j++) acc[i][j] = 0.f;

    for (int c0 = 0; c0 < C; c0 += 32) {
        for (int q = t; q < 32 * 224; q += 256) {
            int j = q / 224, p = q - j * 224;
            xs[q] = (p < PT) ? tf[(size_t)(b * C + c0 + j) * PT + p] : 0.f;
        }
        for (int q = t; q < 2048; q += 256) {
            int cc = q >> 5, j = q & 31;
            ws[j * 68 + cc] = w_t[cc * C + c0 + j];
        }
        __syncthreads();
#pragma unroll 4
        for (int j = 0; j < 32; j++) {
            float4 wa = *(const float4*)&ws[j * 68 + ccg * 8];
            float4 wb = *(const float4*)&ws[j * 68 + ccg * 8 + 4];
            float wv[8] = {wa.x, wa.y, wa.z, wa.w, wb.x, wb.y, wb.z, wb.w};
            float xv[7];
#pragma unroll
            for (int p = 0; p < 7; p++) xv[p] = xs[j * 224 + pt + 32 * p];
#pragma unroll
            for (int i = 0; i < 8; i++)
#pragma unroll
                for (int p = 0; p < 7; p++) acc[i][p] += wv[i] * xv[p];
        }
        __syncthreads();
    }

    // GroupNorm stats: group g = channels {2g, 2g+1}, 392 values each
    float* red  = smem;          // [64][33]
    float* red2 = smem + 64*33;  // [64][33]
#pragma unroll
    for (int i = 0; i < 8; i++) {
        float s = 0.f, s2 = 0.f;
#pragma unroll
        for (int p = 0; p < 7; p++) {
            int pp = pt + 32 * p;
            if (pp < PT) { s += acc[i][p]; s2 += acc[i][p] * acc[i][p]; }
        }
        int cc = ccg * 8 + i;
        red[cc * 33 + pt] = s;
        red2[cc * 33 + pt] = s2;
    }
    __syncthreads();
    if (t < 32) {
        float s = 0.f, s2 = 0.f;
        for (int cc = 2 * t; cc < 2 * t + 2; cc++)
            for (int q = 0; q < 32; q++) { s += red[cc * 33 + q]; s2 += red2[cc * 33 + q]; }
        float m = s / 392.f, v = s2 / 392.f - m * m;
        gm[t]  = m;
        grs[t] = rsqrtf(v + EPS);
    }
    __syncthreads();
#pragma unroll
    for (int i = 0; i < 8; i++) {
        int cc = ccg * 8 + i, g = cc >> 1;
        float a  = grs[g] * gnw[cc];
        float bb = gnb[cc] - gm[g] * a;
#pragma unroll
        for (int p = 0; p < 7; p++) {
            int pp = pt + 32 * p;
            if (pp < PT)
                g_t[(b * CCH + cc) * PT + pp] = fmaxf(acc[i][p] * a + bb, 0.f);
        }
    }
}

// =============================================================================
// K2: pooling: t_global (mean over 14x14), t_kernel (exact 2x2 mean -> 7x7)
// =============================================================================
__global__ __launch_bounds__(64) void k_pool()
{
    int cc = blockIdx.x, b = blockIdx.y, t = threadIdx.x;
    __shared__ float sp[64];
    const float* tp = g_t + (b * CCH + cc) * PT;
    float v = 0.f;
    if (t < 49) {
        int ky = t / 7, kx = t - 7 * (t / 7);
        const float* r0 = tp + (2 * ky) * 14 + 2 * kx;
        v = 0.25f * (r0[0] + r0[1] + r0[14] + r0[15]);
        g_tk[(b * CCH + cc) * 49 + t] = v;
    }
    sp[t] = v;
    __syncthreads();
    for (int o = 32; o > 0; o >>= 1) { if (t < o) sp[t] += sp[t + o]; __syncthreads(); }
    if (t == 0) g_tg[b * CCH + cc] = sp[0] * (1.f / 49.f);  // mean of all 196
}

// =============================================================================
// K3: search conv1x1 (256->64), raw output -> g_z.  8cc x 8px register tile.
// grid (32 px-tiles, 32 b), 128 threads
// =============================================================================
__global__ __launch_bounds__(128) void k_search(
    const float* __restrict__ sf, const float* __restrict__ w_s)
{
    __shared__ __align__(16) float xs[32 * 128];
    __shared__ __align__(16) float ws[32 * 68];
    int b = blockIdx.y, px0 = blockIdx.x * 128;
    int t = threadIdx.x;
    int ccg = t >> 4;  // 0..7
    int pxg = t & 15;  // 0..15, owns px = px0 + pxg + 16*j

    float acc[8][8];
#pragma unroll
    for (int i = 0; i < 8; i++)
#pragma unroll
        for (int j = 0; j < 8; j++) acc[i][j] = 0.f;

    for (int c0 = 0; c0 < C; c0 += 32) {
        for (int q = t; q < 1024; q += 128) {
            int j = q >> 5, col = q & 31;
            ((float4*)xs)[j * 32 + col] =
                *(const float4*)(sf + (size_t)(b * C + c0 + j) * PS + px0 + col * 4);
        }
        for (int q = t; q < 2048; q += 128) {
            int cc = q >> 5, j = q & 31;
            ws[j * 68 + cc] = w_s[cc * C + c0 + j];
        }
        __syncthreads();
#pragma unroll 4
        for (int j = 0; j < 32; j++) {
            float4 wa = *(const float4*)&ws[j * 68 + ccg * 8];
            float4 wb = *(const float4*)&ws[j * 68 + ccg * 8 + 4];
            float wv[8] = {wa.x, wa.y, wa.z, wa.w, wb.x, wb.y, wb.z, wb.w};
            float xv[8];
#pragma unroll
            for (int i = 0; i < 8; i++) xv[i] = xs[j * 128 + pxg + 16 * i];
#pragma unroll
            for (int ii = 0; ii < 8; ii++)
#pragma unroll
                for (int jj = 0; jj < 8; jj++) acc[ii][jj] += wv[ii] * xv[jj];
        }
        __syncthreads();
    }
#pragma unroll
    for (int ii = 0; ii < 8; ii++) {
        int cc = ccg * 8 + ii;
#pragma unroll
        for (int jj = 0; jj < 8; jj++)
            g_z[(size_t)(b * CCH + cc) * PS + px0 + pxg + 16 * jj] = acc[ii][jj];
    }
}

// =============================================================================
// K4: GroupNorm stats over (2 channels x 4096 px), deterministic tree reduce.
// Emits per-channel affine alpha/beta (normalize = alpha*x + beta).
// =============================================================================
__global__ __launch_bounds__(128) void k_stats(
    const float* __restrict__ src, const float* __restrict__ gnw,
    const float* __restrict__ gnb, float* __restrict__ ab)
{
    int g = blockIdx.x, b = blockIdx.y, t = threadIdx.x;
    const float* base = src + (size_t)(b * CCH + 2 * g) * PS;
    float s = 0.f, s2 = 0.f;
    for (int i = t; i < 2 * PS; i += 128) { float v = base[i]; s += v; s2 += v * v; }
    __shared__ float r1[128], r2[128];
    r1[t] = s; r2[t] = s2;
    __syncthreads();
    for (int o = 64; o > 0; o >>= 1) {
        if (t < o) { r1[t] += r1[t + o]; r2[t] += r2[t + o]; }
        __syncthreads();
    }
    if (t < 2) {
        int cc = 2 * g + t;
        float m = r1[0] / (2.f * PS);
        float v = r2[0] / (2.f * PS) - m * m;
        float a = rsqrtf(v + EPS) * gnw[cc];
        ab[(b * CCH + cc) * 2]     = a;
        ab[(b * CCH + cc) * 2 + 1] = gnb[cc] - m * a;
    }
}

// =============================================================================
// K5: depthwise 7x7 correlation + global correlation (folded into center tap).
// Normalizes z -> s = relu(alpha*z+beta) on the fly into a zero-padded halo.
// grid (64 cc, 32 b), 256 threads; 49 weights kept in registers.
// =============================================================================
__global__ __launch_bounds__(256) void k_dw()
{
    __shared__ float s[70 * 71];
    __shared__ float wsh[50];
    int cc = blockIdx.x, b = blockIdx.y, t = threadIdx.x;
    int bc = b * CCH + cc;
    size_t base = (size_t)bc * PS;
    float al = g_ab_s[bc * 2], be = g_ab_s[bc * 2 + 1];
    if (t < 49) wsh[t] = g_tk[bc * 49 + t];
    if (t == 49) wsh[49] = g_tg[bc];
    for (int i = t; i < 70 * 71; i += 256) s[i] = 0.f;
    __syncthreads();
    for (int i = t; i < PS; i += 256) {
        int yy = i >> 6, xx = i & 63;
        s[(yy + 3) * 71 + xx + 3] = fmaxf(al * g_z[base + i] + be, 0.f);
    }
    __syncthreads();
    float wr[49];
#pragma unroll
    for (int k = 0; k < 49; k++) wr[k] = wsh[k];
    wr[24] += wsh[49];  // global corr == extra center tap
    for (int gi = t; gi < 1024; gi += 256) {
        int yy = gi >> 4, xb = (gi & 15) << 2;
        float a0 = 0.f, a1 = 0.f, a2 = 0.f, a3 = 0.f;
#pragma unroll
        for (int dy = 0; dy < 7; dy++) {
            const float* row = &s[(yy + dy) * 71 + xb];
            float v[10];
#pragma unroll
            for (int d = 0; d < 10; d++) v[d] = row[d];
#pragma unroll
            for (int dx = 0; dx < 7; dx++) {
                float ww = wr[dy * 7 + dx];
                a0 += ww * v[dx];     a1 += ww * v[dx + 1];
                a2 += ww * v[dx + 2]; a3 += ww * v[dx + 3];
            }
        }
        float4 r = {a0, a1, a2, a3};
        *(float4*)&g_corr[base + yy * 64 + xb] = r;
    }
}

// =============================================================================
// K6: weight transpose for conv3x3: w_p1[co][cin][k] -> g_wT[cin][k][co]
// =============================================================================
__global__ __launch_bounds__(256) void k_wtrans(const float* __restrict__ w1)
{
    int i = blockIdx.x * 256 + threadIdx.x;
    if (i < CCH * CCH * 9) {
        int co = i / 576;
        int rem = i - co * 576;
        int cin = rem / 9, k = rem - 9 * cin;
        g_wT[(cin * 9 + k) * CCH + co] = w1[i];
    }
}

// =============================================================================
// K7: conv3x3 (64->64), SAME padding, raw output -> g_y.
// 16x16 px tile per block, 8cin chunk staged with halo, 8co x 8px reg tile.
// grid (16 tiles, 32 b), 256 threads
// =============================================================================
__global__ __launch_bounds__(256) void k_conv3()
{
    __shared__ __align__(16) float hs[8][18 * 19];
    __shared__ __align__(16) float wsm[8][9][64];
    int tile = blockIdx.x, b = blockIdx.y;
    int y0 = (tile >> 2) * 16, x0 = (tile & 3) * 16;
    int t = threadIdx.x;
    int ccg = t >> 5;        // 0..7
    int tx  = t & 31;
    int pr0 = tx >> 4;       // 0..1: owns rows pr0 + 2*i
    int pc  = tx & 15;       // 0..15: column within tile

    float acc[8][8];
#pragma unroll
    for (int i = 0; i < 8; i++)
#pragma unroll
        for (int j = 0; j < 8; j++) acc[i][j] = 0.f;

    for (int c0 = 0; c0 < CCH; c0 += 8) {
        for (int q = t; q < 8 * 324; q += 256) {
            int j = q / 324, rc = q - j * 324;
            int r = rc / 18, c2 = rc - 18 * r;
            int gy = y0 - 1 + r, gx = x0 - 1 + c2;
            float v = 0.f;
            if (gy >= 0 && gy < HS && gx >= 0 && gx < HS)
                v = g_corr[(size_t)(b * CCH + c0 + j) * PS + gy * HS + gx];
            hs[j][r * 19 + c2] = v;
        }
        for (int q = t; q < 8 * 9 * 64; q += 256)
            ((float*)wsm)[q] = g_wT[c0 * 9 * 64 + q];
        __syncthreads();
#pragma unroll 1
        for (int j = 0; j < 8; j++) {
#pragma unroll
            for (int k = 0; k < 9; k++) {
                int ky = k / 3, kx = k - 3 * (k / 3);
                float4 wa = *(const float4*)&wsm[j][k][ccg * 8];
                float4 wb = *(const float4*)&wsm[j][k][ccg * 8 + 4];
                float wv[8] = {wa.x, wa.y, wa.z, wa.w, wb.x, wb.y, wb.z, wb.w};
                float xv[8];
#pragma unroll
                for (int i = 0; i < 8; i++)
                    xv[i] = hs[j][(pr0 + 2 * i + ky) * 19 + pc + kx];
#pragma unroll
                for (int ii = 0; ii < 8; ii++)
#pragma unroll
                    for (int i = 0; i < 8; i++) acc[ii][i] += wv[ii] * xv[i];
            }
        }
        __syncthreads();
    }
#pragma unroll
    for (int ii = 0; ii < 8; ii++) {
        int co = ccg * 8 + ii;
#pragma unroll
        for (int i = 0; i < 8; i++) {
            int py = y0 + pr0 + 2 * i, px = x0 + pc;
            g_y[(size_t)(b * CCH + co) * PS + py * HS + px] = acc[ii][i];
        }
    }
}

// =============================================================================
// K8: final: out = b2 + sum_cc w2[cc] * relu(alpha*y + beta)
// =============================================================================
__global__ __launch_bounds__(256) void k_final(
    const float* __restrict__ w2, const float* __restrict__ b2,
    float* __restrict__ out)
{
    __shared__ float swv[64], sa[64], sb[64];
    int b = blockIdx.y, p0 = blockIdx.x * 256, t = threadIdx.x;
    if (t < 64) {
        swv[t] = w2[t];
        sa[t] = g_ab_p[(b * CCH + t) * 2];
        sb[t] = g_ab_p[(b * CCH + t) * 2 + 1];
    }
    __syncthreads();
    int p = p0 + t;
    float o = b2[0];
#pragma unroll 4
    for (int cc = 0; cc < 64; cc++) {
        float v = g_y[(size_t)(b * CCH + cc) * PS + p];
        o += swv[cc] * fmaxf(sa[cc] * v + sb[cc], 0.f);
    }
    out[b * PS + p] = o;
}

// =============================================================================
extern "C" void kernel_launch(void* const* d_in, const int* in_sizes, int n_in,
                              void* d_out, int out_size)
{
    (void)in_sizes; (void)n_in; (void)out_size;
    const float* tf  = (const float*)d_in[0];   // template_feat
    const float* sf  = (const float*)d_in[1];   // search_feat
    const float* w_t = (const float*)d_in[2];
    const float* gtw = (const float*)d_in[3];
    const float* gtb = (const float*)d_in[4];
    const float* w_s = (const float*)d_in[5];
    const float* gsw = (const float*)d_in[6];
    const float* gsb = (const float*)d_in[7];
    const float* w1  = (const float*)d_in[8];   // w_p1
    const float* gpw = (const float*)d_in[9];
    const float* gpb = (const float*)d_in[10];
    const float* w2  = (const float*)d_in[11];  // w_p2
    const float* b2  = (const float*)d_in[12];  // b_p2
    float* out = (float*)d_out;

    float *pz, *py, *pabs, *pabp;
    cudaGetSymbolAddress((void**)&pz,   g_z);
    cudaGetSymbolAddress((void**)&py,   g_y);
    cudaGetSymbolAddress((void**)&pabs, g_ab_s);
    cudaGetSymbolAddress((void**)&pabp, g_ab_p);

    k_template<<<B, 256>>>(tf, w_t, gtw, gtb);
    k_pool<<<dim3(CCH, B), 64>>>();
    k_search<<<dim3(32, B), 128>>>(sf, w_s);
    k_stats<<<dim3(32, B), 128>>>(pz, gsw, gsb, pabs);
    k_dw<<<dim3(CCH, B), 256>>>();
    k_wtrans<<<(CCH * CCH * 9 + 255) / 256, 256>>>(w1);
    k_conv3<<<dim3(16, B), 256>>>();
    k_stats<<<dim3(32, B), 128>>>(py, gpw, gpb, pabp);
    k_final<<<dim3(16, B), 256>>>(w2, b2, out);
}

// round 9
// speedup vs baseline: 1.3066x; 1.3066x over previous
#include <cuda_runtime.h>
#include <cuda_bf16.h>
#include <cstdint>

#define EPS 1e-5f
#define B   32
#define C   256
#define CCH 64
#define PS  4096
#define PT  196

#define SWZ(x) ((x) ^ (((x) >> 3) & 0x70))

// tcgen05 is arch-specific ("a") — real asm only in arch-specific device
// passes; plain compute_103/sm_103 passes get inert stubs (never executed).
#if !defined(__CUDA_ARCH__) || defined(__CUDA_ARCH_FEAT_SM103_ALL) || \
    defined(__CUDA_ARCH_FEAT_SM100_ALL) || defined(__CUDA_ARCH_FEAT_SM101_ALL)
#define HAS_TC 1
#else
#define HAS_TC 0
#endif

// ---------------- scratch ----------------
__device__ float g_t   [B * CCH * PT];
__device__ float g_tk  [B * CCH * 49];
__device__ float g_tg  [B * CCH];
__device__ float g_z   [(size_t)B * CCH * PS];
__device__ float g_y   [(size_t)B * CCH * PS];
__device__ float g_ab_s[B * CCH * 2];
__device__ float g_ab_p[B * CCH * 2];
__device__ __align__(16) __nv_bfloat16 g_ch[(size_t)B * CCH * PS];
__device__ __align__(16) __nv_bfloat16 g_cl[(size_t)B * CCH * PS];
__device__ uint4 g_wsA[4096];   // search A: 4 chunks x [128m x 64k] bf16, swizzled
__device__ uint4 g_w1A[9216];   // conv3 A: 9 taps x [128m x 64k] bf16, swizzled

// ---------------- PTX helpers ----------------
__device__ __forceinline__ uint32_t smem_u32(const void* p) {
    uint32_t a;
    asm("{ .reg .u64 t; cvta.to.shared.u64 t, %1; cvt.u32.u64 %0, t; }" : "=r"(a) : "l"(p));
    return a;
}
__device__ __forceinline__ uint32_t elect1() {
    uint32_t p;
    asm volatile("{ .reg .pred p; elect.sync _|p, 0xFFFFFFFF; selp.b32 %0, 1, 0, p; }" : "=r"(p));
    return p;
}
__device__ __forceinline__ void tm_alloc(uint32_t sa, uint32_t n) {
#if HAS_TC
    asm volatile("tcgen05.alloc.cta_group::1.sync.aligned.shared::cta.b32 [%0], %1;"
                 :: "r"(sa), "r"(n) : "memory");
#endif
}
__device__ __forceinline__ void tm_relinq() {
#if HAS_TC
    asm volatile("tcgen05.relinquish_alloc_permit.cta_group::1.sync.aligned;");
#endif
}
__device__ __forceinline__ void tm_dealloc(uint32_t b_, uint32_t n) {
#if HAS_TC
    asm volatile("tcgen05.dealloc.cta_group::1.sync.aligned.b32 %0, %1;" :: "r"(b_), "r"(n));
#endif
}
__device__ __forceinline__ void mbar_init(uint32_t mb, uint32_t c) {
    asm volatile("mbarrier.init.shared.b64 [%0], %1;" :: "r"(mb), "r"(c) : "memory");
}
__device__ __forceinline__ void mbar_inval(uint32_t mb) {
    asm volatile("mbarrier.inval.shared.b64 [%0];" :: "r"(mb) : "memory");
}
__device__ __forceinline__ void mbar_wait(uint32_t mb, uint32_t par) {
    asm volatile(
        "{\n\t.reg .pred P1;\n\t"
        "LW%=:\n\t"
        "mbarrier.try_wait.parity.acquire.cta.shared::cta.b64 P1, [%0], %1, 0x989680;\n\t"
        "@P1 bra LD%=;\n\t"
        "bra LW%=;\n\t"
        "LD%=:\n\t}"
        :: "r"(mb), "r"(par) : "memory");
}
__device__ __forceinline__ void tm_commit(uint32_t mb) {
#if HAS_TC
    asm volatile("tcgen05.commit.cta_group::1.mbarrier::arrive::one.shared::cluster.b64 [%0];"
                 :: "r"(mb) : "memory");
#else
    asm volatile("mbarrier.arrive.shared.b64 _, [%0];" :: "r"(mb) : "memory");
#endif
}
__device__ __forceinline__ void fence_async() {
    asm volatile("fence.proxy.async.shared::cta;" ::: "memory");
}
__device__ __forceinline__ void tm_fence_after() {
#if HAS_TC
    asm volatile("tcgen05.fence::after_thread_sync;" ::: "memory");
#endif
}
__device__ __forceinline__ void tm_wait_ld() {
#if HAS_TC
    asm volatile("tcgen05.wait::ld.sync.aligned;" ::: "memory");
#endif
}
__device__ __forceinline__ void mma_f16(uint32_t d, uint64_t ad, uint64_t bd,
                                        uint32_t idesc, uint32_t en) {
#if HAS_TC
    asm volatile(
        "{\n\t.reg .pred p;\n\tsetp.ne.u32 p, %4, 0;\n\t"
        "tcgen05.mma.cta_group::1.kind::f16 [%0], %1, %2, %3, {%5, %5, %5, %5}, p;\n\t}"
        :: "r"(d), "l"(ad), "l"(bd), "r"(idesc), "r"(en), "r"(0u) : "memory");
#else
    (void)d; (void)ad; (void)bd; (void)idesc; (void)en;
#endif
}
__device__ __forceinline__ void ldtm32(uint32_t* r, uint32_t a) {
#if HAS_TC
    asm volatile(
        "tcgen05.ld.sync.aligned.32x32b.x32.b32 "
        "{%0,%1,%2,%3,%4,%5,%6,%7,%8,%9,%10,%11,%12,%13,%14,%15,"
        "%16,%17,%18,%19,%20,%21,%22,%23,%24,%25,%26,%27,%28,%29,%30,%31}, [%32];"
        : "=r"(r[0]), "=r"(r[1]), "=r"(r[2]), "=r"(r[3]), "=r"(r[4]), "=r"(r[5]), "=r"(r[6]), "=r"(r[7]),
          "=r"(r[8]), "=r"(r[9]), "=r"(r[10]), "=r"(r[11]), "=r"(r[12]), "=r"(r[13]), "=r"(r[14]), "=r"(r[15]),
          "=r"(r[16]), "=r"(r[17]), "=r"(r[18]), "=r"(r[19]), "=r"(r[20]), "=r"(r[21]), "=r"(r[22]), "=r"(r[23]),
          "=r"(r[24]), "=r"(r[25]), "=r"(r[26]), "=r"(r[27]), "=r"(r[28]), "=r"(r[29]), "=r"(r[30]), "=r"(r[31])
        : "r"(a));
#else
    for (int i = 0; i < 32; i++) r[i] = 0;
    (void)a;
#endif
}
__device__ __forceinline__ uint64_t desc_k(uint32_t a) {  // K-major SW128: LBO=1, SBO=64
    return ((uint64_t)((a >> 4) & 0x3FFF)) | (1ull << 16) | (64ull << 32) | (1ull << 46) | (2ull << 61);
}
// c=F32, a=BF16 K-major, b=BF16 K-major, N=64, M=128 (all fields test-verified)
#define IDESC 0x8100490u

// =============================================================================
// K1: template conv1x1 + GN + ReLU (fp32; tiny — proven)
// =============================================================================
__global__ __launch_bounds__(256) void k_template(
    const float* __restrict__ tf, const float* __restrict__ w_t,
    const float* __restrict__ gnw, const float* __restrict__ gnb)
{
    __shared__ __align__(16) float smem[32 * 224 + 32 * 68];
    float* xs = smem;
    float* ws = smem + 32 * 224;
    __shared__ float gm[32], grs[32];
    int b = blockIdx.x, t = threadIdx.x;
    int ccg = t >> 5, pt = t & 31;
    float acc[8][7];
#pragma unroll
    for (int i = 0; i < 8; i++)
#pragma unroll
        for (int j = 0; j < 7; j++) acc[i][j] = 0.f;
    for (int c0 = 0; c0 < C; c0 += 32) {
        for (int q = t; q < 32 * 224; q += 256) {
            int j = q / 224, p = q - j * 224;
            xs[q] = (p < PT) ? tf[(size_t)(b * C + c0 + j) * PT + p] : 0.f;
        }
        for (int q = t; q < 2048; q += 256) {
            int cc = q >> 5, j = q & 31;
            ws[j * 68 + cc] = w_t[cc * C + c0 + j];
        }
        __syncthreads();
#pragma unroll 4
        for (int j = 0; j < 32; j++) {
            float4 wa = *(const float4*)&ws[j * 68 + ccg * 8];
            float4 wb = *(const float4*)&ws[j * 68 + ccg * 8 + 4];
            float wv[8] = {wa.x, wa.y, wa.z, wa.w, wb.x, wb.y, wb.z, wb.w};
            float xv[7];
#pragma unroll
            for (int p = 0; p < 7; p++) xv[p] = xs[j * 224 + pt + 32 * p];
#pragma unroll
            for (int i = 0; i < 8; i++)
#pragma unroll
                for (int p = 0; p < 7; p++) acc[i][p] += wv[i] * xv[p];
        }
        __syncthreads();
    }
    float* red = smem;
    float* red2 = smem + 64 * 33;
#pragma unroll
    for (int i = 0; i < 8; i++) {
        float s = 0.f, s2 = 0.f;
#pragma unroll
        for (int p = 0; p < 7; p++) {
            int pp = pt + 32 * p;
            if (pp < PT) { s += acc[i][p]; s2 += acc[i][p] * acc[i][p]; }
        }
        int cc = ccg * 8 + i;
        red[cc * 33 + pt] = s;
        red2[cc * 33 + pt] = s2;
    }
    __syncthreads();
    if (t < 32) {
        float s = 0.f, s2 = 0.f;
        for (int cc = 2 * t; cc < 2 * t + 2; cc++)
            for (int q = 0; q < 32; q++) { s += red[cc * 33 + q]; s2 += red2[cc * 33 + q]; }
        float m = s / 392.f, v = s2 / 392.f - m * m;
        gm[t] = m; grs[t] = rsqrtf(v + EPS);
    }
    __syncthreads();
#pragma unroll
    for (int i = 0; i < 8; i++) {
        int cc = ccg * 8 + i, g = cc >> 1;
        float a = grs[g] * gnw[cc];
        float bb = gnb[cc] - gm[g] * a;
#pragma unroll
        for (int p = 0; p < 7; p++) {
            int pp = pt + 32 * p;
            if (pp < PT) g_t[(b * CCH + cc) * PT + pp] = fmaxf(acc[i][p] * a + bb, 0.f);
        }
    }
}

// =============================================================================
// K2: pooling
// =============================================================================
__global__ __launch_bounds__(64) void k_pool()
{
    int cc = blockIdx.x, b = blockIdx.y, t = threadIdx.x;
    __shared__ float sp[64];
    const float* tp = g_t + (b * CCH + cc) * PT;
    float v = 0.f;
    if (t < 49) {
        int ky = t / 7, kx = t - 7 * (t / 7);
        const float* r0 = tp + (2 * ky) * 14 + 2 * kx;
        v = 0.25f * (r0[0] + r0[1] + r0[14] + r0[15]);
        g_tk[(b * CCH + cc) * 49 + t] = v;
    }
    sp[t] = v;
    __syncthreads();
    for (int o = 32; o > 0; o >>= 1) { if (t < o) sp[t] += sp[t + o]; __syncthreads(); }
    if (t == 0) g_tg[b * CCH + cc] = sp[0] * (1.f / 49.f);
}

// =============================================================================
// K2b: weight prep -> stacked hi/lo A tiles (swizzled K-major) for both MMAs
// =============================================================================
__global__ __launch_bounds__(256) void k_wprep(const float* __restrict__ ws,
                                               const float* __restrict__ w1)
{
    int t = blockIdx.x * 256 + threadIdx.x;
    if (t < 32768) {
        int chunk = t >> 13, r = t & 8191, m = r >> 6, k = r & 63;
        int cc = m & 63;
        float w = ws[cc * C + chunk * 64 + k];
        __nv_bfloat16 h = __float2bfloat16(w);
        __nv_bfloat16 v = (m < 64) ? h : __float2bfloat16(w - __bfloat162float(h));
        ((__nv_bfloat16*)g_wsA)[(chunk << 13) + (SWZ(m * 128 + k * 2) >> 1)] = v;
    }
    if (t < 73728) {
        int tap = t >> 13, r = t & 8191, m = r >> 6, k = r & 63;
        int co = m & 63;
        float w = w1[(co * 64 + k) * 9 + tap];
        __nv_bfloat16 h = __float2bfloat16(w);
        __nv_bfloat16 v = (m < 64) ? h : __float2bfloat16(w - __bfloat162float(h));
        ((__nv_bfloat16*)g_w1A)[(tap << 13) + (SWZ(m * 128 + k * 2) >> 1)] = v;
    }
}

// =============================================================================
// K3: search conv1x1 on tcgen05. Block: 256px (4 N=64 tiles), full C=256.
// A (weights, K-major) resident 64KB; B = [64 px rows][64 ch cols] K-major,
// hi/lo, double-buffered, built by transpose-scatter from native sf layout.
// =============================================================================
#define S_A    0
#define S_B    65536
#define S_CTRL 98304
#define SMEM_S 98368

__global__ __launch_bounds__(256) void k_search_mma(const float* __restrict__ sf)
{
    extern __shared__ __align__(1024) char smem[];
    uint32_t sb = smem_u32(smem);
    int b = blockIdx.y, pg = blockIdx.x, t = threadIdx.x;
    int wid = t >> 5, lane = t & 31;
    uint32_t mb0 = sb + S_CTRL + 8, mb1 = sb + S_CTRL + 16;

    if (wid == 0) { tm_alloc(sb + S_CTRL, 256); tm_relinq(); }
    if (t == 0) { mbar_init(mb0, 1); mbar_init(mb1, 1); }
    __syncthreads();
    uint32_t tmem;
    asm volatile("ld.shared.b32 %0, [%1];" : "=r"(tmem) : "r"(sb + S_CTRL));

    {   // stage A (64KB)
        uint4* dst = (uint4*)(smem + S_A);
        for (int i = t; i < 4096; i += 256) dst[i] = g_wsA[i];
    }

    int c = t >> 2, q = t & 3;       // c = channel column, q = 16px group
    int pc0 = 0, pc1 = 0;
    for (int it = 0; it < 16; it++) {
        int tile = it >> 2, chunk = it & 3, buf = it & 1;
        if (it >= 2) {
            if (buf == 0) { mbar_wait(mb0, pc0 & 1); pc0++; }
            else          { mbar_wait(mb1, pc1 & 1); pc1++; }
        }
        {   // stage B transposed: value(ch c, px p) -> row p, col c (hi & lo)
            const float4* p4 = (const float4*)(sf +
                (size_t)(b * C + chunk * 64 + c) * PS + pg * 256 + tile * 64 + q * 16);
            float4 f0 = p4[0], f1 = p4[1], f2 = p4[2], f3 = p4[3];
            float f[16] = {f0.x, f0.y, f0.z, f0.w, f1.x, f1.y, f1.z, f1.w,
                           f2.x, f2.y, f2.z, f2.w, f3.x, f3.y, f3.z, f3.w};
            uint32_t bh = S_B + buf * 16384, bl = bh + 8192;
#pragma unroll
            for (int j = 0; j < 16; j++) {
                int p = q * 16 + j;
                uint32_t off = (uint32_t)(p * 128) +
                               (((uint32_t)(2 * c)) ^ (((uint32_t)(p & 7)) << 4));
                float v = f[j];
                __nv_bfloat16 h = __float2bfloat16(v);
                *(unsigned short*)(smem + bh + off) = __bfloat16_as_ushort(h);
                *(unsigned short*)(smem + bl + off) =
                    __bfloat16_as_ushort(__float2bfloat16(v - __bfloat162float(h)));
            }
        }
        fence_async();
        __syncthreads();
        if (wid == 0 && elect1()) {
            uint64_t ad = desc_k(sb + S_A + chunk * 16384);
            uint64_t bh = desc_k(sb + S_B + buf * 16384);
            uint64_t bl = desc_k(sb + S_B + buf * 16384 + 8192);
            uint32_t d = tmem + tile * 64;
#pragma unroll
            for (int ks = 0; ks < 4; ks++)
                mma_f16(d, ad + ks * 2, bh + ks * 2, IDESC, !(chunk == 0 && ks == 0));
#pragma unroll
            for (int ks = 0; ks < 4; ks++)
                mma_f16(d, ad + ks * 2, bl + ks * 2, IDESC, 1u);
            tm_commit(buf ? mb1 : mb0);
        }
    }
    mbar_wait(mb0, pc0 & 1);
    mbar_wait(mb1, pc1 & 1);
    __syncthreads();
    tm_fence_after();

    float* epi = (float*)(smem + S_A);  // [64][65] (A no longer needed)
    for (int tile = 0; tile < 4; tile++) {
        uint32_t r0[32], r1[32];
        if (wid < 4) {
            ldtm32(r0, tmem + tile * 64);
            ldtm32(r1, tmem + tile * 64 + 32);
            tm_wait_ld();
        }
        if (wid >= 2 && wid < 4) {      // rows 64..127 = Wl part
            int cc = (wid - 2) * 32 + lane;
#pragma unroll
            for (int j = 0; j < 32; j++) {
                epi[cc * 65 + j]      = __uint_as_float(r0[j]);
                epi[cc * 65 + 32 + j] = __uint_as_float(r1[j]);
            }
        }
        __syncthreads();
        if (wid < 2) {                  // rows 0..63 = Wh part; sum & store
            int cc = wid * 32 + lane;
            float4* o4 = (float4*)(g_z + (size_t)(b * CCH + cc) * PS + pg * 256 + tile * 64);
#pragma unroll
            for (int jq = 0; jq < 16; jq++) {
                int j0 = jq * 4;
                float4 v;
                v.x = __uint_as_float(j0 < 32 ? r0[j0] : r1[j0 - 32])         + epi[cc * 65 + j0];
                v.y = __uint_as_float(j0 + 1 < 32 ? r0[j0 + 1] : r1[j0 - 31]) + epi[cc * 65 + j0 + 1];
                v.z = __uint_as_float(j0 + 2 < 32 ? r0[j0 + 2] : r1[j0 - 30]) + epi[cc * 65 + j0 + 2];
                v.w = __uint_as_float(j0 + 3 < 32 ? r0[j0 + 3] : r1[j0 - 29]) + epi[cc * 65 + j0 + 3];
                o4[jq] = v;
            }
        }
        __syncthreads();
    }
    if (t == 0) { mbar_inval(mb0); mbar_inval(mb1); }
    __syncthreads();
    if (wid == 0) tm_dealloc(tmem, 256);
}

// =============================================================================
// K4: GN stats -> per-channel affine
// =============================================================================
__global__ __launch_bounds__(128) void k_stats(
    const float* __restrict__ src, const float* __restrict__ gnw,
    const float* __restrict__ gnb, float* __restrict__ ab)
{
    int g = blockIdx.x, b = blockIdx.y, t = threadIdx.x;
    const float* base = src + (size_t)(b * CCH + 2 * g) * PS;
    float s = 0.f, s2 = 0.f;
    for (int i = t; i < 2 * PS; i += 128) { float v = base[i]; s += v; s2 += v * v; }
    __shared__ float r1[128], r2[128];
    r1[t] = s; r2[t] = s2;
    __syncthreads();
    for (int o = 64; o > 0; o >>= 1) {
        if (t < o) { r1[t] += r1[t + o]; r2[t] += r2[t + o]; }
        __syncthreads();
    }
    if (t < 2) {
        int cc = 2 * g + t;
        float m = r1[0] / (2.f * PS);
        float v = r2[0] / (2.f * PS) - m * m;
        float a = rsqrtf(v + EPS) * gnw[cc];
        ab[(b * CCH + cc) * 2] = a;
        ab[(b * CCH + cc) * 2 + 1] = gnb[cc] - m * a;
    }
}

// =============================================================================
// K5: depthwise 7x7 + global corr; outputs hi/lo bf16 corr (conv3 MMA input)
// =============================================================================
__global__ __launch_bounds__(256) void k_dw()
{
    __shared__ float s[70 * 71];
    __shared__ float wsh[50];
    int cc = blockIdx.x, b = blockIdx.y, t = threadIdx.x;
    int bc = b * CCH + cc;
    size_t base = (size_t)bc * PS;
    float al = g_ab_s[bc * 2], be = g_ab_s[bc * 2 + 1];
    if (t < 49) wsh[t] = g_tk[bc * 49 + t];
    if (t == 49) wsh[49] = g_tg[bc];
    for (int i = t; i < 70 * 71; i += 256) s[i] = 0.f;
    __syncthreads();
    for (int i = t; i < PS; i += 256) {
        int yy = i >> 6, xx = i & 63;
        s[(yy + 3) * 71 + xx + 3] = fmaxf(al * g_z[base + i] + be, 0.f);
    }
    __syncthreads();
    float wr[49];
#pragma unroll
    for (int qk = 0; qk < 49; qk++) wr[qk] = wsh[qk];
    wr[24] += wsh[49];
    for (int gi = t; gi < 1024; gi += 256) {
        int yy = gi >> 4, xb = (gi & 15) << 2;
        float a0 = 0.f, a1 = 0.f, a2 = 0.f, a3 = 0.f;
#pragma unroll
        for (int dy = 0; dy < 7; dy++) {
            const float* row = &s[(yy + dy) * 71 + xb];
            float v[10];
#pragma unroll
            for (int d = 0; d < 10; d++) v[d] = row[d];
#pragma unroll
            for (int dx = 0; dx < 7; dx++) {
                float ww = wr[dy * 7 + dx];
                a0 += ww * v[dx];     a1 += ww * v[dx + 1];
                a2 += ww * v[dx + 2]; a3 += ww * v[dx + 3];
            }
        }
        __nv_bfloat16 h0 = __float2bfloat16(a0), h1 = __float2bfloat16(a1);
        __nv_bfloat16 h2 = __float2bfloat16(a2), h3 = __float2bfloat16(a3);
        uint2 hp, lp;
        hp.x = (uint32_t)__bfloat16_as_ushort(h0) | ((uint32_t)__bfloat16_as_ushort(h1) << 16);
        hp.y = (uint32_t)__bfloat16_as_ushort(h2) | ((uint32_t)__bfloat16_as_ushort(h3) << 16);
        lp.x = (uint32_t)__bfloat16_as_ushort(__float2bfloat16(a0 - __bfloat162float(h0))) |
               ((uint32_t)__bfloat16_as_ushort(__float2bfloat16(a1 - __bfloat162float(h1))) << 16);
        lp.y = (uint32_t)__bfloat16_as_ushort(__float2bfloat16(a2 - __bfloat162float(h2))) |
               ((uint32_t)__bfloat16_as_ushort(__float2bfloat16(a3 - __bfloat162float(h3))) << 16);
        size_t o = base + yy * 64 + xb;
        *(uint2*)(g_ch + o) = hp;
        *(uint2*)(g_cl + o) = lp;
    }
}

// =============================================================================
// K7: conv3x3 on tcgen05. Block: 2 output rows. 24 K-major B tiles
// [64 px][64 ch] (4 src rows x 3 x-shifts x hi/lo) built ONCE via transpose-
// scatter; per tap only the 16KB A tile streams (double-buffered).
// Tile (pr, xs, r): row n holds value at source pixel n + xs - 1 of src row r.
// =============================================================================
#define C_B    0
#define C_A    196608
#define C_CTRL 229376
#define SMEM_C 229440

__global__ __launch_bounds__(256) void k_conv3_mma()
{
    extern __shared__ __align__(1024) char smem[];
    uint32_t sb = smem_u32(smem);
    int b = blockIdx.y, y0 = blockIdx.x * 2, t = threadIdx.x;
    int wid = t >> 5, lane = t & 31;
    uint32_t mb0 = sb + C_CTRL + 8, mb1 = sb + C_CTRL + 16;

    if (wid == 0) { tm_alloc(sb + C_CTRL, 128); tm_relinq(); }
    if (t == 0) { mbar_init(mb0, 1); mbar_init(mb1, 1); }
    __syncthreads();
    uint32_t tmem;
    asm volatile("ld.shared.b32 %0, [%1];" : "=r"(tmem) : "r"(sb + C_CTRL));

    // zero the 16 never-written border rows (xs=0 row 0; xs=2 row 63)
    for (int i = t; i < 512; i += 256) {
        int idx = i >> 5, w = i & 31;
        int pr = idx & 1, r = (idx >> 1) & 3, e = idx >> 3;
        uint32_t tb = (uint32_t)(((pr * 3 + (e ? 2 : 0)) * 4 + r) * 8192) + (e ? 63 * 128 : 0);
        *(uint32_t*)(smem + C_B + tb + w * 4) = 0;
    }

    int c = t >> 2, q = t & 3;
    for (int r = 0; r < 4; r++) {
        int sy = y0 - 1 + r;
        uint32_t vh[8], vl[8];
        if ((unsigned)sy < 64u) {
            const uint4* ph = (const uint4*)(g_ch + (size_t)(b * CCH + c) * PS + sy * 64 + q * 16);
            const uint4* pl = (const uint4*)(g_cl + (size_t)(b * CCH + c) * PS + sy * 64 + q * 16);
            uint4 a = ph[0], bb = ph[1];
            vh[0] = a.x; vh[1] = a.y; vh[2] = a.z; vh[3] = a.w;
            vh[4] = bb.x; vh[5] = bb.y; vh[6] = bb.z; vh[7] = bb.w;
            a = pl[0]; bb = pl[1];
            vl[0] = a.x; vl[1] = a.y; vl[2] = a.z; vl[3] = a.w;
            vl[4] = bb.x; vl[5] = bb.y; vl[6] = bb.z; vl[7] = bb.w;
        } else {
#pragma unroll
            for (int j = 0; j < 8; j++) { vh[j] = 0; vl[j] = 0; }
        }
#pragma unroll
        for (int j = 0; j < 16; j++) {
            int p = q * 16 + j;
            unsigned short hv = (unsigned short)((j & 1) ? (vh[j >> 1] >> 16) : (vh[j >> 1] & 0xFFFFu));
            unsigned short lv = (unsigned short)((j & 1) ? (vl[j >> 1] >> 16) : (vl[j >> 1] & 0xFFFFu));
#pragma unroll
            for (int xs = 0; xs < 3; xs++) {
                int n = p + 1 - xs;
                if ((unsigned)n < 64u) {
                    uint32_t off = (uint32_t)(n * 128) +
                                   (((uint32_t)(2 * c)) ^ (((uint32_t)(n & 7)) << 4));
                    *(unsigned short*)(smem + C_B + (uint32_t)((xs * 4 + r) * 8192) + off) = hv;
                    *(unsigned short*)(smem + C_B + (uint32_t)(((3 + xs) * 4 + r) * 8192) + off) = lv;
                }
            }
        }
    }
    fence_async();
    __syncthreads();

    int pc0 = 0, pc1 = 0;
    for (int tap = 0; tap < 9; tap++) {
        int ky = tap / 3, kx = tap - 3 * ky, buf = tap & 1;
        if (tap >= 2) {
            if (buf == 0) { mbar_wait(mb0, pc0 & 1); pc0++; }
            else          { mbar_wait(mb1, pc1 & 1); pc1++; }
        }
        {   // stage A[buf]
            uint4* dst = (uint4*)(smem + C_A + buf * 16384);
            const uint4* src = g_w1A + tap * 1024;
            for (int i = t; i < 1024; i += 256) dst[i] = src[i];
        }
        fence_async();
        __syncthreads();
        if (wid == 0 && elect1()) {
            uint64_t ad = desc_k(sb + C_A + buf * 16384);
#pragma unroll
            for (int tile = 0; tile < 2; tile++) {
                int r = tile + ky;
                uint64_t bh = desc_k(sb + C_B + (uint32_t)((kx * 4 + r) * 8192));
                uint64_t bl = desc_k(sb + C_B + (uint32_t)(((3 + kx) * 4 + r) * 8192));
                uint32_t d = tmem + tile * 64;
#pragma unroll
                for (int ks = 0; ks < 4; ks++)
                    mma_f16(d, ad + ks * 2, bh + ks * 2, IDESC, !(tap == 0 && ks == 0));
#pragma unroll
                for (int ks = 0; ks < 4; ks++)
                    mma_f16(d, ad + ks * 2, bl + ks * 2, IDESC, 1u);
            }
            tm_commit(buf ? mb1 : mb0);
        }
    }
    mbar_wait(mb0, pc0 & 1);
    mbar_wait(mb1, pc1 & 1);
    __syncthreads();
    tm_fence_after();

    float* epi = (float*)(smem + C_A);  // [64][65]
    for (int tile = 0; tile < 2; tile++) {
        uint32_t r0[32], r1[32];
        if (wid < 4) {
            ldtm32(r0, tmem + tile * 64);
            ldtm32(r1, tmem + tile * 64 + 32);
            tm_wait_ld();
        }
        if (wid >= 2 && wid < 4) {
            int cc = (wid - 2) * 32 + lane;
#pragma unroll
            for (int j = 0; j < 32; j++) {
                epi[cc * 65 + j]      = __uint_as_float(r0[j]);
                epi[cc * 65 + 32 + j] = __uint_as_float(r1[j]);
            }
        }
        __syncthreads();
        if (wid < 2) {
            int cc = wid * 32 + lane;
            float4* o4 = (float4*)(g_y + (size_t)(b * CCH + cc) * PS + (y0 + tile) * 64);
#pragma unroll
            for (int jq = 0; jq < 16; jq++) {
                int j0 = jq * 4;
                float4 v;
                v.x = __uint_as_float(j0 < 32 ? r0[j0] : r1[j0 - 32])         + epi[cc * 65 + j0];
                v.y = __uint_as_float(j0 + 1 < 32 ? r0[j0 + 1] : r1[j0 - 31]) + epi[cc * 65 + j0 + 1];
                v.z = __uint_as_float(j0 + 2 < 32 ? r0[j0 + 2] : r1[j0 - 30]) + epi[cc * 65 + j0 + 2];
                v.w = __uint_as_float(j0 + 3 < 32 ? r0[j0 + 3] : r1[j0 - 29]) + epi[cc * 65 + j0 + 3];
                o4[jq] = v;
            }
        }
        __syncthreads();
    }
    if (t == 0) { mbar_inval(mb0); mbar_inval(mb1); }
    __syncthreads();
    if (wid == 0) tm_dealloc(tmem, 128);
}

// =============================================================================
// K8: final: out = b2 + sum_cc w2[cc] * relu(alpha*y + beta)
// =============================================================================
__global__ __launch_bounds__(256) void k_final(
    const float* __restrict__ w2, const float* __restrict__ b2,
    float* __restrict__ out)
{
    __shared__ float swv[64], sa[64], sb_[64];
    int b = blockIdx.y, p0 = blockIdx.x * 256, t = threadIdx.x;
    if (t < 64) {
        swv[t] = w2[t];
        sa[t] = g_ab_p[(b * CCH + t) * 2];
        sb_[t] = g_ab_p[(b * CCH + t) * 2 + 1];
    }
    __syncthreads();
    int p = p0 + t;
    float o = b2[0];
#pragma unroll 4
    for (int cc = 0; cc < 64; cc++) {
        float v = g_y[(size_t)(b * CCH + cc) * PS + p];
        o += swv[cc] * fmaxf(sa[cc] * v + sb_[cc], 0.f);
    }
    out[b * PS + p] = o;
}

// =============================================================================
extern "C" void kernel_launch(void* const* d_in, const int* in_sizes, int n_in,
                              void* d_out, int out_size)
{
    (void)in_sizes; (void)n_in; (void)out_size;
    const float* tf  = (const float*)d_in[0];
    const float* sf  = (const float*)d_in[1];
    const float* w_t = (const float*)d_in[2];
    const float* gtw = (const float*)d_in[3];
    const float* gtb = (const float*)d_in[4];
    const float* w_s = (const float*)d_in[5];
    const float* gsw = (const float*)d_in[6];
    const float* gsb = (const float*)d_in[7];
    const float* w1  = (const float*)d_in[8];
    const float* gpw = (const float*)d_in[9];
    const float* gpb = (const float*)d_in[10];
    const float* w2  = (const float*)d_in[11];
    const float* b2  = (const float*)d_in[12];
    float* out = (float*)d_out;

    float *pz, *py, *pabs, *pabp;
    cudaGetSymbolAddress((void**)&pz,   g_z);
    cudaGetSymbolAddress((void**)&py,   g_y);
    cudaGetSymbolAddress((void**)&pabs, g_ab_s);
    cudaGetSymbolAddress((void**)&pabp, g_ab_p);

    cudaFuncSetAttribute(k_search_mma, cudaFuncAttributeMaxDynamicSharedMemorySize, SMEM_S);
    cudaFuncSetAttribute(k_conv3_mma,  cudaFuncAttributeMaxDynamicSharedMemorySize, SMEM_C);

    k_template<<<B, 256>>>(tf, w_t, gtw, gtb);
    k_pool<<<dim3(CCH, B), 64>>>();
    k_wprep<<<288, 256>>>(w_s, w1);
    k_search_mma<<<dim3(16, B), 256, SMEM_S>>>(sf);
    k_stats<<<dim3(32, B), 128>>>(pz, gsw, gsb, pabs);
    k_dw<<<dim3(CCH, B), 256>>>();
    k_conv3_mma<<<dim3(32, B), 256, SMEM_C>>>();
    k_stats<<<dim3(32, B), 128>>>(py, gpw, gpb, pabp);
    k_final<<<dim3(16, B), 256>>>(w2, b2, out);
}